// round 6
// baseline (speedup 1.0000x reference)
#include <cuda_runtime.h>
#include <cuda_fp16.h>
#include <math.h>

#define HC 64
#define NF 64
#define NG 5
#define SL 20
#define ZD 148
#define BN_EPS 1e-5f
#define MAX_N 50000
#define MAX_E 800000

typedef unsigned long long ull;

// Scratch (allocation-free rule: __device__ globals)
__device__ __align__(16) float g_agg[MAX_N * NF];         // per-layer aggregation
__device__ __align__(16) float g_projA[MAX_N * 128];      // fp32 [N][Af(64)|As(64)] (biases incl.)
__device__ __align__(16) uint2 g_projB[MAX_N * 32];       // fp16 [N][lane] = (f2,s2) of Bf|Bs
__device__ __align__(16) float g_ea[(size_t)MAX_E * SL];  // relu(edge_attr@short_w)
__device__ __align__(16) uint2 g_ep[(size_t)MAX_E * 32];  // fp16 [e][lane] = (f2,s2) of ea@W3
__device__ __align__(16) float g_sums[2 * NF];            // sum / sumsq
__device__ int  g_deg[MAX_N];
__device__ int  g_off[MAX_N];
__device__ int  g_cur[MAX_N];
__device__ __align__(8) int2 g_es[MAX_E];                 // bucket order: (src, edge_id)

// ---------------- packed f32x2 helpers ----------------
__device__ __forceinline__ ull fma2(ull a, ull b, ull c) {
    ull d;
    asm("fma.rn.f32x2 %0, %1, %2, %3;" : "=l"(d) : "l"(a), "l"(b), "l"(c));
    return d;
}
__device__ __forceinline__ ull pack2(float v) {
    ull r;
    asm("mov.b64 %0, {%1, %1};" : "=l"(r) : "f"(v));
    return r;
}
__device__ __forceinline__ float2 unpack2(ull v) {
    float2 r;
    asm("mov.b64 {%0, %1}, %2;" : "=f"(r.x), "=f"(r.y) : "l"(v));
    return r;
}
__device__ __forceinline__ float msg_fn(float f, float s) {
    float sig = __fdividef(1.f, 1.f + __expf(-f));
    float sp  = fmaxf(s, 0.f) + __logf(1.f + __expf(-fabsf(s)));
    return sig * sp;
}

// ---------------------------------------------------------------------------
// Kernel 1: fused [zero_deg | lin0 | ea]
#define K1_ZB 64
#define K1_LB 592
#define K1_EB 1184
#define K1_GRID (K1_ZB + K1_LB + K1_EB)

__global__ __launch_bounds__(256) void fused_pre_kernel(
    const float* __restrict__ h, const float* __restrict__ lw,
    const float* __restrict__ lb, float* __restrict__ out,
    const float* __restrict__ attr, const float* __restrict__ sw,
    const float* __restrict__ sb, int N, int E)
{
    __shared__ float smem[64 * 64 + 64];
    int tid = threadIdx.x;
    int b = blockIdx.x;

    if (b < K1_ZB) {
        // zero degree histogram
        int stride = K1_ZB * 256;
        for (int i = b * 256 + tid; i < N; i += stride) g_deg[i] = 0;
        return;
    }
    b -= K1_ZB;
    if (b < K1_LB) {
        // out = relu(h @ lw + lb)
        float* sW = smem;
        float* sbv = smem + 64 * 64;
        for (int i = tid; i < 64 * 64; i += 256) sW[i] = lw[i];
        if (tid < 64) sbv[tid] = lb[tid];
        __syncthreads();
        int c = tid & 63, rr = tid >> 6;
        for (int r0 = b * 4; r0 < N; r0 += K1_LB * 4) {
            int r = r0 + rr;
            if (r < N) {
                const float* hr = h + (size_t)r * 64;
                float acc = sbv[c];
#pragma unroll 16
                for (int k = 0; k < 64; k++)
                    acc = fmaf(__ldg(hr + k), sW[k * 64 + c], acc);
                out[(size_t)r * 64 + c] = fmaxf(acc, 0.f);
            }
        }
        return;
    }
    b -= K1_LB;
    {
        // g_ea = relu(attr @ sw + sb)
        float* w = smem;
        float* bb = smem + NG * SL;
        if (tid < NG * SL) w[tid] = sw[tid];
        if (tid < SL)      bb[tid] = sb[tid];
        __syncthreads();
        int stride = K1_EB * 256;
        for (int e = b * 256 + tid; e < E; e += stride) {
            float a[NG];
#pragma unroll
            for (int g = 0; g < NG; g++) a[g] = __ldg(attr + (size_t)e * NG + g);
            float4* dst = (float4*)(g_ea + (size_t)e * SL);
#pragma unroll
            for (int q = 0; q < 5; q++) {
                float o[4];
#pragma unroll
                for (int j = 0; j < 4; j++) {
                    float acc = bb[q * 4 + j];
#pragma unroll
                    for (int g = 0; g < NG; g++)
                        acc = fmaf(a[g], w[g * SL + q * 4 + j], acc);
                    o[j] = fmaxf(acc, 0.f);
                }
                dst[q] = make_float4(o[0], o[1], o[2], o[3]);
            }
        }
    }
}

// ---------------------------------------------------------------------------
__global__ __launch_bounds__(256) void hist_kernel(const int* __restrict__ ei, int E) {
    int stride = gridDim.x * blockDim.x;
    for (int e = blockIdx.x * blockDim.x + threadIdx.x; e < E; e += stride)
        atomicAdd(&g_deg[__ldg(ei + E + e)], 1);
}

__global__ __launch_bounds__(1024) void scan_kernel(int N) {
    __shared__ int part[1024];
    int t = threadIdx.x;
    int C = (N + 1023) >> 10;
    int lo = t * C, hi = min(lo + C, N);
    int s = 0;
    for (int i = lo; i < hi; i++) s += g_deg[i];
    part[t] = s;
    __syncthreads();
    for (int d = 1; d < 1024; d <<= 1) {
        int v = (t >= d) ? part[t - d] : 0;
        __syncthreads();
        part[t] += v;
        __syncthreads();
    }
    int run = part[t] - s;
    for (int i = lo; i < hi; i++) {
        int d = g_deg[i];
        g_off[i] = run;
        g_cur[i] = run;
        run += d;
    }
}

// ---------------------------------------------------------------------------
// Kernel 4 (and 7): fused [scatter? | node_proj | eproj] for one layer.
// scatter: bucket edges by dst into g_es (only on first layer).
// node_proj: g_projA[n] = out[n]@[W1f|W1s] + bias (fp32); g_projB[n] = fp16(out[n]@[W2f|W2s])
// eproj: g_ep[e] = fp16(ea[e] @ [W3f|W3s])  (edge order)
#define K4_SB 1024
#define K4_PB 592
#define K4_QB 1024

__global__ __launch_bounds__(256) void fused_mid_kernel(
    const int* __restrict__ ei, const float* __restrict__ out,
    const float* __restrict__ Wf, const float* __restrict__ bf,
    const float* __restrict__ Ws, const float* __restrict__ bs,
    int N, int E, int SB)
{
    int tid = threadIdx.x;
    int b = blockIdx.x;

    if (b < SB) {
        int stride = SB * 256;
        for (int e = b * 256 + tid; e < E; e += stride) {
            int dst = __ldg(ei + E + e);
            int pos = atomicAdd(&g_cur[dst], 1);
            g_es[pos] = make_int2(__ldg(ei + e), e);
        }
        return;
    }
    b -= SB;

    if (b < K4_PB) {
        // node projections
        if (b == 0 && tid < 2 * NF) g_sums[tid] = 0.f;
        __shared__ __align__(16) float sOut[16 * 64];
        int c = tid;
        const float* base; int col; float bias; int isA, seg;
        if (c < 64)       { base = Wf;           col = c;       bias = __ldg(bf + c);      isA = 1; seg = 0; }
        else if (c < 128) { base = Ws;           col = c - 64;  bias = __ldg(bs + c - 64); isA = 1; seg = 1; }
        else if (c < 192) { base = Wf + 64 * 64; col = c - 128; bias = 0.f;                isA = 0; seg = 0; }
        else              { base = Ws + 64 * 64; col = c - 192; bias = 0.f;                isA = 0; seg = 1; }
        float w[64];
#pragma unroll
        for (int k = 0; k < 64; k++) w[k] = __ldg(base + k * 64 + col);
        // fp16 half index for B parts: pair-interleaved (f0 f1 s0 s1 | f2 f3 s2 s3 | ...)
        int hidx = 4 * (col >> 1) + (col & 1) + (seg ? 2 : 0);

        for (int r0 = b * 16; r0 < N; r0 += K4_PB * 16) {
            __syncthreads();
            for (int i = tid; i < 16 * 16; i += 256) {
                int r = i >> 4, q = i & 15;
                int rr = r0 + r;
                float4 v = (rr < N) ? ((const float4*)out)[(size_t)rr * 16 + q]
                                    : make_float4(0.f, 0.f, 0.f, 0.f);
                ((float4*)sOut)[r * 16 + q] = v;
            }
            __syncthreads();
            float acc[16];
#pragma unroll
            for (int r = 0; r < 16; r++) acc[r] = bias;
#pragma unroll
            for (int k4 = 0; k4 < 16; k4++) {
#pragma unroll
                for (int r = 0; r < 16; r++) {
                    float4 z = ((const float4*)sOut)[r * 16 + k4];
                    acc[r] = fmaf(z.x, w[k4 * 4 + 0], acc[r]);
                    acc[r] = fmaf(z.y, w[k4 * 4 + 1], acc[r]);
                    acc[r] = fmaf(z.z, w[k4 * 4 + 2], acc[r]);
                    acc[r] = fmaf(z.w, w[k4 * 4 + 3], acc[r]);
                }
            }
#pragma unroll
            for (int r = 0; r < 16; r++) {
                int rr = r0 + r;
                if (rr < N) {
                    if (isA) g_projA[(size_t)rr * 128 + seg * 64 + col] = acc[r];
                    else ((__half*)g_projB)[(size_t)rr * 128 + hidx] = __float2half(acc[r]);
                }
            }
        }
        return;
    }
    b -= K4_PB;
    {
        // per-edge ea @ [W3f|W3s] -> fp16, edge order. Warp handles 2 edges.
        const float* W3f = Wf + 128 * 64;
        const float* W3s = Ws + 128 * 64;
        int lane = tid & 31;
        int c2 = lane * 2;
        ull wf[SL], ws[SL];
#pragma unroll
        for (int k = 0; k < SL; k++) {
            wf[k] = __ldg((const ull*)(W3f + k * 64 + c2));
            ws[k] = __ldg((const ull*)(W3s + k * 64 + c2));
        }
        long warp  = ((long)b * 256 + tid) >> 5;
        long nwarp = (long)K4_QB * 8;
        long npairs = ((long)E + 1) >> 1;
        for (long p = warp; p < npairs; p += nwarp) {
            long e0 = 2 * p, e1 = e0 + 1;
            bool v1 = (e1 < E);
            long e1c = v1 ? e1 : e0;
            const float4* ea0 = (const float4*)(g_ea + e0  * SL);
            const float4* ea1 = (const float4*)(g_ea + e1c * SL);
            ull f0 = 0, q0 = 0, f1 = 0, q1 = 0;
#pragma unroll
            for (int kk = 0; kk < 5; kk++) {
                float4 A0 = __ldg(ea0 + kk);
                float4 A1 = __ldg(ea1 + kk);
                float a0v[4] = {A0.x, A0.y, A0.z, A0.w};
                float a1v[4] = {A1.x, A1.y, A1.z, A1.w};
#pragma unroll
                for (int j = 0; j < 4; j++) {
                    int k = kk * 4 + j;
                    ull a0 = pack2(a0v[j]);
                    ull a1 = pack2(a1v[j]);
                    f0 = fma2(a0, wf[k], f0);
                    q0 = fma2(a0, ws[k], q0);
                    f1 = fma2(a1, wf[k], f1);
                    q1 = fma2(a1, ws[k], q1);
                }
            }
            float2 F0 = unpack2(f0), Q0 = unpack2(q0);
            __half2 hf0 = __floats2half2_rn(F0.x, F0.y);
            __half2 hq0 = __floats2half2_rn(Q0.x, Q0.y);
            uint2 o0; o0.x = *(unsigned*)&hf0; o0.y = *(unsigned*)&hq0;
            g_ep[e0 * 32 + lane] = o0;
            if (v1) {
                float2 F1 = unpack2(f1), Q1 = unpack2(q1);
                __half2 hf1 = __floats2half2_rn(F1.x, F1.y);
                __half2 hq1 = __floats2half2_rn(Q1.x, Q1.y);
                uint2 o1; o1.x = *(unsigned*)&hf1; o1.y = *(unsigned*)&hq1;
                g_ep[e1 * 32 + lane] = o1;
            }
        }
    }
}

// ---------------------------------------------------------------------------
// edge_agg: one warp per node. 3 LDG.64 per edge. Fused BN stats.
//   f = Af[n] + half(Bf[src] + epF[e]) ; s = As[n] + half(Bs[src] + epS[e])
__global__ __launch_bounds__(256) void edge_agg_kernel(int N)
{
    int lane = threadIdx.x & 31;
    int c2 = lane * 2;

    int warp  = (blockIdx.x * 256 + threadIdx.x) >> 5;
    int nwarp = gridDim.x * 8;

    float sx = 0.f, sy = 0.f, qx = 0.f, qy = 0.f;
    const float2* pA = (const float2*)g_projA;  // 64 float2 per node

    for (int n = warp; n < N; n += nwarp) {
        int beg = __ldg(&g_off[n]);
        int end = beg + __ldg(&g_deg[n]);

        float2 af = __ldg(pA + (size_t)n * 64 + lane);       // Af pair (bias incl.)
        float2 as_ = __ldg(pA + (size_t)n * 64 + 32 + lane); // As pair (bias incl.)

        float accx = 0.f, accy = 0.f;
        int i = beg;
        for (; i + 1 < end; i += 2) {
            int2 se0 = __ldg(&g_es[i]);
            int2 se1 = __ldg(&g_es[i + 1]);
            uint2 b0 = __ldg(&g_projB[(size_t)se0.x * 32 + lane]);
            uint2 b1 = __ldg(&g_projB[(size_t)se1.x * 32 + lane]);
            uint2 p0 = __ldg(&g_ep[(size_t)se0.y * 32 + lane]);
            uint2 p1 = __ldg(&g_ep[(size_t)se1.y * 32 + lane]);

            __half2 hf0 = __hadd2(*(__half2*)&b0.x, *(__half2*)&p0.x);
            __half2 hs0 = __hadd2(*(__half2*)&b0.y, *(__half2*)&p0.y);
            __half2 hf1 = __hadd2(*(__half2*)&b1.x, *(__half2*)&p1.x);
            __half2 hs1 = __hadd2(*(__half2*)&b1.y, *(__half2*)&p1.y);
            float2 ff0 = __half22float2(hf0), ss0 = __half22float2(hs0);
            float2 ff1 = __half22float2(hf1), ss1 = __half22float2(hs1);

            accx += msg_fn(af.x + ff0.x, as_.x + ss0.x);
            accy += msg_fn(af.y + ff0.y, as_.y + ss0.y);
            accx += msg_fn(af.x + ff1.x, as_.x + ss1.x);
            accy += msg_fn(af.y + ff1.y, as_.y + ss1.y);
        }
        if (i < end) {
            int2 se0 = __ldg(&g_es[i]);
            uint2 b0 = __ldg(&g_projB[(size_t)se0.x * 32 + lane]);
            uint2 p0 = __ldg(&g_ep[(size_t)se0.y * 32 + lane]);
            __half2 hf0 = __hadd2(*(__half2*)&b0.x, *(__half2*)&p0.x);
            __half2 hs0 = __hadd2(*(__half2*)&b0.y, *(__half2*)&p0.y);
            float2 ff0 = __half22float2(hf0), ss0 = __half22float2(hs0);
            accx += msg_fn(af.x + ff0.x, as_.x + ss0.x);
            accy += msg_fn(af.y + ff0.y, as_.y + ss0.y);
        }

        *(float2*)&g_agg[(size_t)n * 64 + c2] = make_float2(accx, accy);
        sx += accx; sy += accy;
        qx = fmaf(accx, accx, qx);
        qy = fmaf(accy, accy, qy);
    }

    atomicAdd(&g_sums[c2],          sx);
    atomicAdd(&g_sums[c2 + 1],      sy);
    atomicAdd(&g_sums[64 + c2],     qx);
    atomicAdd(&g_sums[64 + c2 + 1], qy);
}

// ---------------------------------------------------------------------------
// out = out + relu( BN(agg) + out )
__global__ __launch_bounds__(256) void bn_apply_kernel(
    const float* __restrict__ gamma, const float* __restrict__ beta,
    float* __restrict__ out, int N, float invN)
{
    int tid = threadIdx.x;
    int c0 = (tid & 15) * 4;
    float mul[4], add[4];
#pragma unroll
    for (int j = 0; j < 4; j++) {
        float mean = g_sums[c0 + j] * invN;
        float var  = fmaf(-mean, mean, g_sums[64 + c0 + j] * invN);
        float inv  = rsqrtf(var + BN_EPS);
        float m = inv * __ldg(gamma + c0 + j);
        mul[j] = m;
        add[j] = __ldg(beta + c0 + j) - mean * m;
    }
    float4* o4 = (float4*)out;
    const float4* a4 = (const float4*)g_agg;
    int total = N * 16;
    int stride = gridDim.x * 256;
    for (int i = blockIdx.x * 256 + tid; i < total; i += stride) {
        float4 a = a4[i], o = o4[i], r;
        float bn;
        bn = fmaf(a.x, mul[0], add[0]); r.x = o.x + fmaxf(bn + o.x, 0.f);
        bn = fmaf(a.y, mul[1], add[1]); r.y = o.y + fmaxf(bn + o.y, 0.f);
        bn = fmaf(a.z, mul[2], add[2]); r.z = o.z + fmaxf(bn + o.z, 0.f);
        bn = fmaf(a.w, mul[3], add[3]); r.w = o.w + fmaxf(bn + o.w, 0.f);
        o4[i] = r;
    }
}

// ---------------------------------------------------------------------------
extern "C" void kernel_launch(void* const* d_in, const int* in_sizes, int n_in,
                              void* d_out, int out_size)
{
    const float* h      = (const float*)d_in[0];
    const int*   ei     = (const int*)  d_in[1];
    // d_in[2] = edge_weight (unused by reference)
    const float* eattr  = (const float*)d_in[3];
    const float* lin0_w = (const float*)d_in[4];
    const float* lin0_b = (const float*)d_in[5];
    const float* shw    = (const float*)d_in[6];
    const float* shb    = (const float*)d_in[7];
    const float* linf_w = (const float*)d_in[8];
    const float* linf_b = (const float*)d_in[9];
    const float* lins_w = (const float*)d_in[10];
    const float* lins_b = (const float*)d_in[11];
    const float* gamma  = (const float*)d_in[12];
    const float* beta   = (const float*)d_in[13];

    int N = in_sizes[0] / HC;
    int E = in_sizes[1] / 2;
    float* out = (float*)d_out;

    // 1: [zero_deg | lin0 | ea]
    fused_pre_kernel<<<K1_GRID, 256>>>(h, lin0_w, lin0_b, out, eattr, shw, shb, N, E);
    // 2, 3: degree histogram + offsets
    hist_kernel<<<1480, 256>>>(ei, E);
    scan_kernel<<<1, 1024>>>(N);

    for (int l = 0; l < 2; l++) {
        const float* Wf = linf_w + (size_t)l * ZD * NF;
        const float* Ws = lins_w + (size_t)l * ZD * NF;
        int SB = (l == 0) ? K4_SB : 0;  // scatter only once
        // 4 / 7: [scatter? | node_proj | eproj]
        fused_mid_kernel<<<SB + K4_PB + K4_QB, 256>>>(
            ei, out, Wf, linf_b + l * NF, Ws, lins_b + l * NF, N, E, SB);
        // 5 / 8: gather + aggregate + BN stats
        edge_agg_kernel<<<1480, 256>>>(N);
        // 6 / 9: BN apply + residuals
        bn_apply_kernel<<<592, 256>>>(gamma + l * NF, beta + l * NF, out, N, 1.f / (float)N);
    }
}

// round 7
// speedup vs baseline: 1.2362x; 1.2362x over previous
#include <cuda_runtime.h>
#include <cuda_fp16.h>
#include <math.h>

#define HC 64
#define NF 64
#define NG 5
#define SL 20
#define ZD 148
#define BN_EPS 1e-5f
#define MAX_N 50000
#define MAX_E 800000

typedef unsigned long long ull;

// Scratch (allocation-free rule: __device__ globals)
__device__ __align__(16) float g_agg[MAX_N * NF];         // per-layer aggregation
__device__ __align__(16) float g_projA[MAX_N * 128];      // fp32 [N][Af(64)|As(64)] (biases incl.)
__device__ __align__(16) uint2 g_projB[MAX_N * 32];       // fp16 [N][lane] = (f2,s2) of Bf|Bs
__device__ __align__(16) float g_ea[(size_t)MAX_E * SL];  // relu(edge_attr@short_w)
__device__ __align__(16) uint2 g_ep[(size_t)MAX_E * 32];  // fp16 [e][lane] = (f2,s2) of ea@W3
__device__ __align__(16) float g_sums[2 * NF];            // sum / sumsq
__device__ int  g_deg[MAX_N];
__device__ int  g_off[MAX_N];
__device__ int  g_cur[MAX_N];
__device__ __align__(8) int2 g_es[MAX_E];                 // bucket order: (src, edge_id)

// ---------------- packed f32x2 helpers ----------------
__device__ __forceinline__ ull fma2(ull a, ull b, ull c) {
    ull d;
    asm("fma.rn.f32x2 %0, %1, %2, %3;" : "=l"(d) : "l"(a), "l"(b), "l"(c));
    return d;
}
__device__ __forceinline__ ull pack2(float v) {
    ull r;
    asm("mov.b64 %0, {%1, %1};" : "=l"(r) : "f"(v));
    return r;
}
__device__ __forceinline__ float2 unpack2(ull v) {
    float2 r;
    asm("mov.b64 {%0, %1}, %2;" : "=f"(r.x), "=f"(r.y) : "l"(v));
    return r;
}
__device__ __forceinline__ float msg_fn(float f, float s) {
    float sig = __fdividef(1.f, 1.f + __expf(-f));
    float sp  = fmaxf(s, 0.f) + __logf(1.f + __expf(-fabsf(s)));
    return sig * sp;
}

// ---------------------------------------------------------------------------
// Launch 1: fused [zero_deg | lin0 | ea]  (uniform low reg pressure, safe fusion)
#define K1_ZB 64
#define K1_LB 592
#define K1_EB 1184
#define K1_GRID (K1_ZB + K1_LB + K1_EB)

__global__ __launch_bounds__(256) void fused_pre_kernel(
    const float* __restrict__ h, const float* __restrict__ lw,
    const float* __restrict__ lb, float* __restrict__ out,
    const float* __restrict__ attr, const float* __restrict__ sw,
    const float* __restrict__ sb, int N, int E)
{
    __shared__ float smem[64 * 64 + 64];
    int tid = threadIdx.x;
    int b = blockIdx.x;

    if (b < K1_ZB) {
        int stride = K1_ZB * 256;
        for (int i = b * 256 + tid; i < N; i += stride) g_deg[i] = 0;
        return;
    }
    b -= K1_ZB;
    if (b < K1_LB) {
        float* sW = smem;
        float* sbv = smem + 64 * 64;
        for (int i = tid; i < 64 * 64; i += 256) sW[i] = lw[i];
        if (tid < 64) sbv[tid] = lb[tid];
        __syncthreads();
        int c = tid & 63, rr = tid >> 6;
        for (int r0 = b * 4; r0 < N; r0 += K1_LB * 4) {
            int r = r0 + rr;
            if (r < N) {
                const float* hr = h + (size_t)r * 64;
                float acc = sbv[c];
#pragma unroll 16
                for (int k = 0; k < 64; k++)
                    acc = fmaf(__ldg(hr + k), sW[k * 64 + c], acc);
                out[(size_t)r * 64 + c] = fmaxf(acc, 0.f);
            }
        }
        return;
    }
    b -= K1_LB;
    {
        float* w = smem;
        float* bb = smem + NG * SL;
        if (tid < NG * SL) w[tid] = sw[tid];
        if (tid < SL)      bb[tid] = sb[tid];
        __syncthreads();
        int stride = K1_EB * 256;
        for (int e = b * 256 + tid; e < E; e += stride) {
            float a[NG];
#pragma unroll
            for (int g = 0; g < NG; g++) a[g] = __ldg(attr + (size_t)e * NG + g);
            float4* dst = (float4*)(g_ea + (size_t)e * SL);
#pragma unroll
            for (int q = 0; q < 5; q++) {
                float o[4];
#pragma unroll
                for (int j = 0; j < 4; j++) {
                    float acc = bb[q * 4 + j];
#pragma unroll
                    for (int g = 0; g < NG; g++)
                        acc = fmaf(a[g], w[g * SL + q * 4 + j], acc);
                    o[j] = fmaxf(acc, 0.f);
                }
                dst[q] = make_float4(o[0], o[1], o[2], o[3]);
            }
        }
    }
}

// ---------------------------------------------------------------------------
__global__ __launch_bounds__(256) void hist_kernel(const int* __restrict__ ei, int E) {
    int stride = gridDim.x * blockDim.x;
    for (int e = blockIdx.x * blockDim.x + threadIdx.x; e < E; e += stride)
        atomicAdd(&g_deg[__ldg(ei + E + e)], 1);
}

__global__ __launch_bounds__(1024) void scan_kernel(int N) {
    __shared__ int part[1024];
    int t = threadIdx.x;
    int C = (N + 1023) >> 10;
    int lo = t * C, hi = min(lo + C, N);
    int s = 0;
    for (int i = lo; i < hi; i++) s += g_deg[i];
    part[t] = s;
    __syncthreads();
    for (int d = 1; d < 1024; d <<= 1) {
        int v = (t >= d) ? part[t - d] : 0;
        __syncthreads();
        part[t] += v;
        __syncthreads();
    }
    int run = part[t] - s;
    for (int i = lo; i < hi; i++) {
        int d = g_deg[i];
        g_off[i] = run;
        g_cur[i] = run;
        run += d;
    }
}

__global__ __launch_bounds__(256) void scatter_kernel(const int* __restrict__ ei, int E) {
    int stride = gridDim.x * blockDim.x;
    for (int e = blockIdx.x * blockDim.x + threadIdx.x; e < E; e += stride) {
        int dst = __ldg(ei + E + e);
        int pos = atomicAdd(&g_cur[dst], 1);
        g_es[pos] = make_int2(__ldg(ei + e), e);
    }
}

// ---------------------------------------------------------------------------
// eproj (standalone): g_ep[e] = fp16( ea[e] @ [W3f|W3s] ), edge order.
// Warp = 2 edges/iter; lane owns channel pair c2 = 2*lane. Weights in regs.
__global__ __launch_bounds__(128) void eproj_kernel(
    const float* __restrict__ W3f, const float* __restrict__ W3s, int E)
{
    int lane = threadIdx.x & 31;
    int c2 = lane * 2;
    ull wf[SL], ws[SL];
#pragma unroll
    for (int k = 0; k < SL; k++) {
        wf[k] = __ldg((const ull*)(W3f + k * 64 + c2));
        ws[k] = __ldg((const ull*)(W3s + k * 64 + c2));
    }

    long warp  = ((long)blockIdx.x * 128 + threadIdx.x) >> 5;
    long nwarp = ((long)gridDim.x * 128) >> 5;
    long npairs = ((long)E + 1) >> 1;

    for (long p = warp; p < npairs; p += nwarp) {
        long e0 = 2 * p, e1 = e0 + 1;
        bool v1 = (e1 < E);
        long e1c = v1 ? e1 : e0;
        const float4* ea0 = (const float4*)(g_ea + e0  * SL);
        const float4* ea1 = (const float4*)(g_ea + e1c * SL);
        ull f0 = 0, q0 = 0, f1 = 0, q1 = 0;
#pragma unroll
        for (int kk = 0; kk < 5; kk++) {
            float4 A0 = __ldg(ea0 + kk);
            float4 A1 = __ldg(ea1 + kk);
            float a0v[4] = {A0.x, A0.y, A0.z, A0.w};
            float a1v[4] = {A1.x, A1.y, A1.z, A1.w};
#pragma unroll
            for (int j = 0; j < 4; j++) {
                int k = kk * 4 + j;
                ull a0 = pack2(a0v[j]);
                ull a1 = pack2(a1v[j]);
                f0 = fma2(a0, wf[k], f0);
                q0 = fma2(a0, ws[k], q0);
                f1 = fma2(a1, wf[k], f1);
                q1 = fma2(a1, ws[k], q1);
            }
        }
        float2 F0 = unpack2(f0), Q0 = unpack2(q0);
        __half2 hf0 = __floats2half2_rn(F0.x, F0.y);
        __half2 hq0 = __floats2half2_rn(Q0.x, Q0.y);
        uint2 o0; o0.x = *(unsigned*)&hf0; o0.y = *(unsigned*)&hq0;
        g_ep[e0 * 32 + lane] = o0;
        if (v1) {
            float2 F1 = unpack2(f1), Q1 = unpack2(q1);
            __half2 hf1 = __floats2half2_rn(F1.x, F1.y);
            __half2 hq1 = __floats2half2_rn(Q1.x, Q1.y);
            uint2 o1; o1.x = *(unsigned*)&hf1; o1.y = *(unsigned*)&hq1;
            g_ep[e1 * 32 + lane] = o1;
        }
    }
}

// ---------------------------------------------------------------------------
// node_proj (standalone): g_projA[n] = out[n]@[W1f|W1s]+bias (fp32);
//                         g_projB[n] = fp16(out[n]@[W2f|W2s]), pair-interleaved.
// Block 0 zeroes g_sums for the layer.
__global__ __launch_bounds__(256) void node_proj_kernel(
    const float* __restrict__ out,
    const float* __restrict__ Wf, const float* __restrict__ bf,
    const float* __restrict__ Ws, const float* __restrict__ bs,
    int N)
{
    int tid = threadIdx.x;
    if (blockIdx.x == 0 && tid < 2 * NF) g_sums[tid] = 0.f;

    __shared__ __align__(16) float sOut[16 * 64];
    int c = tid;
    const float* base; int col; float bias; int isA, seg;
    if (c < 64)       { base = Wf;           col = c;       bias = __ldg(bf + c);      isA = 1; seg = 0; }
    else if (c < 128) { base = Ws;           col = c - 64;  bias = __ldg(bs + c - 64); isA = 1; seg = 1; }
    else if (c < 192) { base = Wf + 64 * 64; col = c - 128; bias = 0.f;                isA = 0; seg = 0; }
    else              { base = Ws + 64 * 64; col = c - 192; bias = 0.f;                isA = 0; seg = 1; }
    float w[64];
#pragma unroll
    for (int k = 0; k < 64; k++) w[k] = __ldg(base + k * 64 + col);
    int hidx = 4 * (col >> 1) + (col & 1) + (seg ? 2 : 0);

    for (int r0 = blockIdx.x * 16; r0 < N; r0 += gridDim.x * 16) {
        __syncthreads();
        for (int i = tid; i < 16 * 16; i += 256) {
            int r = i >> 4, q = i & 15;
            int rr = r0 + r;
            float4 v = (rr < N) ? ((const float4*)out)[(size_t)rr * 16 + q]
                                : make_float4(0.f, 0.f, 0.f, 0.f);
            ((float4*)sOut)[r * 16 + q] = v;
        }
        __syncthreads();
        float acc[16];
#pragma unroll
        for (int r = 0; r < 16; r++) acc[r] = bias;
#pragma unroll
        for (int k4 = 0; k4 < 16; k4++) {
#pragma unroll
            for (int r = 0; r < 16; r++) {
                float4 z = ((const float4*)sOut)[r * 16 + k4];
                acc[r] = fmaf(z.x, w[k4 * 4 + 0], acc[r]);
                acc[r] = fmaf(z.y, w[k4 * 4 + 1], acc[r]);
                acc[r] = fmaf(z.z, w[k4 * 4 + 2], acc[r]);
                acc[r] = fmaf(z.w, w[k4 * 4 + 3], acc[r]);
            }
        }
#pragma unroll
        for (int r = 0; r < 16; r++) {
            int rr = r0 + r;
            if (rr < N) {
                if (isA) g_projA[(size_t)rr * 128 + seg * 64 + col] = acc[r];
                else ((__half*)g_projB)[(size_t)rr * 128 + hidx] = __float2half(acc[r]);
            }
        }
    }
}

// ---------------------------------------------------------------------------
// edge_agg: one warp per node. 3 LDG.64 per edge. Fused BN stats.
__global__ __launch_bounds__(256) void edge_agg_kernel(int N)
{
    int lane = threadIdx.x & 31;
    int c2 = lane * 2;

    int warp  = (blockIdx.x * 256 + threadIdx.x) >> 5;
    int nwarp = gridDim.x * 8;

    float sx = 0.f, sy = 0.f, qx = 0.f, qy = 0.f;
    const float2* pA = (const float2*)g_projA;

    for (int n = warp; n < N; n += nwarp) {
        int beg = __ldg(&g_off[n]);
        int end = beg + __ldg(&g_deg[n]);

        float2 af = __ldg(pA + (size_t)n * 64 + lane);
        float2 as_ = __ldg(pA + (size_t)n * 64 + 32 + lane);

        float accx = 0.f, accy = 0.f;
        int i = beg;
        for (; i + 1 < end; i += 2) {
            int2 se0 = __ldg(&g_es[i]);
            int2 se1 = __ldg(&g_es[i + 1]);
            uint2 b0 = __ldg(&g_projB[(size_t)se0.x * 32 + lane]);
            uint2 b1 = __ldg(&g_projB[(size_t)se1.x * 32 + lane]);
            uint2 p0 = __ldg(&g_ep[(size_t)se0.y * 32 + lane]);
            uint2 p1 = __ldg(&g_ep[(size_t)se1.y * 32 + lane]);

            __half2 hf0 = __hadd2(*(__half2*)&b0.x, *(__half2*)&p0.x);
            __half2 hs0 = __hadd2(*(__half2*)&b0.y, *(__half2*)&p0.y);
            __half2 hf1 = __hadd2(*(__half2*)&b1.x, *(__half2*)&p1.x);
            __half2 hs1 = __hadd2(*(__half2*)&b1.y, *(__half2*)&p1.y);
            float2 ff0 = __half22float2(hf0), ss0 = __half22float2(hs0);
            float2 ff1 = __half22float2(hf1), ss1 = __half22float2(hs1);

            accx += msg_fn(af.x + ff0.x, as_.x + ss0.x);
            accy += msg_fn(af.y + ff0.y, as_.y + ss0.y);
            accx += msg_fn(af.x + ff1.x, as_.x + ss1.x);
            accy += msg_fn(af.y + ff1.y, as_.y + ss1.y);
        }
        if (i < end) {
            int2 se0 = __ldg(&g_es[i]);
            uint2 b0 = __ldg(&g_projB[(size_t)se0.x * 32 + lane]);
            uint2 p0 = __ldg(&g_ep[(size_t)se0.y * 32 + lane]);
            __half2 hf0 = __hadd2(*(__half2*)&b0.x, *(__half2*)&p0.x);
            __half2 hs0 = __hadd2(*(__half2*)&b0.y, *(__half2*)&p0.y);
            float2 ff0 = __half22float2(hf0), ss0 = __half22float2(hs0);
            accx += msg_fn(af.x + ff0.x, as_.x + ss0.x);
            accy += msg_fn(af.y + ff0.y, as_.y + ss0.y);
        }

        *(float2*)&g_agg[(size_t)n * 64 + c2] = make_float2(accx, accy);
        sx += accx; sy += accy;
        qx = fmaf(accx, accx, qx);
        qy = fmaf(accy, accy, qy);
    }

    atomicAdd(&g_sums[c2],          sx);
    atomicAdd(&g_sums[c2 + 1],      sy);
    atomicAdd(&g_sums[64 + c2],     qx);
    atomicAdd(&g_sums[64 + c2 + 1], qy);
}

// ---------------------------------------------------------------------------
// out = out + relu( BN(agg) + out )
__global__ __launch_bounds__(256) void bn_apply_kernel(
    const float* __restrict__ gamma, const float* __restrict__ beta,
    float* __restrict__ out, int N, float invN)
{
    int tid = threadIdx.x;
    int c0 = (tid & 15) * 4;
    float mul[4], add[4];
#pragma unroll
    for (int j = 0; j < 4; j++) {
        float mean = g_sums[c0 + j] * invN;
        float var  = fmaf(-mean, mean, g_sums[64 + c0 + j] * invN);
        float inv  = rsqrtf(var + BN_EPS);
        float m = inv * __ldg(gamma + c0 + j);
        mul[j] = m;
        add[j] = __ldg(beta + c0 + j) - mean * m;
    }
    float4* o4 = (float4*)out;
    const float4* a4 = (const float4*)g_agg;
    int total = N * 16;
    int stride = gridDim.x * 256;
    for (int i = blockIdx.x * 256 + tid; i < total; i += stride) {
        float4 a = a4[i], o = o4[i], r;
        float bn;
        bn = fmaf(a.x, mul[0], add[0]); r.x = o.x + fmaxf(bn + o.x, 0.f);
        bn = fmaf(a.y, mul[1], add[1]); r.y = o.y + fmaxf(bn + o.y, 0.f);
        bn = fmaf(a.z, mul[2], add[2]); r.z = o.z + fmaxf(bn + o.z, 0.f);
        bn = fmaf(a.w, mul[3], add[3]); r.w = o.w + fmaxf(bn + o.w, 0.f);
        o4[i] = r;
    }
}

// ---------------------------------------------------------------------------
extern "C" void kernel_launch(void* const* d_in, const int* in_sizes, int n_in,
                              void* d_out, int out_size)
{
    const float* h      = (const float*)d_in[0];
    const int*   ei     = (const int*)  d_in[1];
    // d_in[2] = edge_weight (unused by reference)
    const float* eattr  = (const float*)d_in[3];
    const float* lin0_w = (const float*)d_in[4];
    const float* lin0_b = (const float*)d_in[5];
    const float* shw    = (const float*)d_in[6];
    const float* shb    = (const float*)d_in[7];
    const float* linf_w = (const float*)d_in[8];
    const float* linf_b = (const float*)d_in[9];
    const float* lins_w = (const float*)d_in[10];
    const float* lins_b = (const float*)d_in[11];
    const float* gamma  = (const float*)d_in[12];
    const float* beta   = (const float*)d_in[13];

    int N = in_sizes[0] / HC;
    int E = in_sizes[1] / 2;
    float* out = (float*)d_out;

    const float* Wf0 = linf_w;
    const float* Ws0 = lins_w;
    const float* Wf1 = linf_w + (size_t)ZD * NF;
    const float* Ws1 = lins_w + (size_t)ZD * NF;

    // 1-3: preprocessing
    fused_pre_kernel<<<K1_GRID, 256>>>(h, lin0_w, lin0_b, out, eattr, shw, shb, N, E);
    hist_kernel<<<1480, 256>>>(ei, E);
    scan_kernel<<<1, 1024>>>(N);

    // ---- layer 0 (eproj as launch #4 for ncu slot-4 capture) ----
    eproj_kernel<<<1776, 128>>>(Wf0 + 128 * NF, Ws0 + 128 * NF, E);        // 4
    scatter_kernel<<<1480, 256>>>(ei, E);                                   // 5
    node_proj_kernel<<<592, 256>>>(out, Wf0, linf_b, Ws0, lins_b, N);       // 6
    edge_agg_kernel<<<1480, 256>>>(N);                                      // 7
    bn_apply_kernel<<<592, 256>>>(gamma, beta, out, N, 1.f / (float)N);     // 8

    // ---- layer 1 ----
    node_proj_kernel<<<592, 256>>>(out, Wf1, linf_b + NF, Ws1, lins_b + NF, N); // 9
    eproj_kernel<<<1776, 128>>>(Wf1 + 128 * NF, Ws1 + 128 * NF, E);             // 10
    edge_agg_kernel<<<1480, 256>>>(N);                                          // 11
    bn_apply_kernel<<<592, 256>>>(gamma + NF, beta + NF, out, N, 1.f / (float)N); // 12
}